// round 13
// baseline (speedup 1.0000x reference)
#include <cuda_runtime.h>
#include <cuda_fp16.h>

#define NN   100000
#define NE   1600000
#define HID  128
#define NOUT 64
#define FULLM 0xffffffffu
#define SCAN_B 1024
#define NB_SCAN ((NN + SCAN_B - 1) / SCAN_B)   // 98
#define WT_PITCH 66
#define GE_BLOCKS ((NE + 255) / 256)           // scatter blocks in merged kernel
#define GG_BLOCKS ((NN + 255) / 256)           // gemm blocks in merged kernel

// ---------------- scratch (device globals; zero-initialized at load) ---------
__device__ int      g_cnt[NN];            // starts 0; re-zeroed by k_scan3
__device__ int      g_tmp[NN];
__device__ int      g_bsum[NB_SCAN];
__device__ int      g_boff[NB_SCAN];
__device__ int      g_rowptr[NN + 1];
__device__ int      g_cursor[NN];
__device__ float    g_dis[NN];            // deg^-1/2 (clamped)
__device__ float    g_d2[NN];             // dis^2
__device__ float    g_inv[NN];            // 1/dis
__device__ int      g_ecol[NE];           // edge cols (CSR order)
__device__ float    g_yf[(size_t)NN * NOUT];     // y = x @ W^T, fp32
__device__ unsigned g_yh[(size_t)NN * 32];       // dis*y in half (64 half)
__device__ unsigned g_hA[(size_t)NN * 32];       // dis^2 * S0
__device__ unsigned g_hB[(size_t)NN * 32];       // dis^2 * S1

__device__ __forceinline__ int clampN(int v) {
    v = v < 0 ? 0 : v;
    return v >= NN ? NN - 1 : v;
}

__device__ __forceinline__ unsigned pack2h(float a, float b) {
    __half2 h = __floats2half2_rn(a, b);
    return *reinterpret_cast<unsigned*>(&h);
}

__device__ __forceinline__ float2 unpack2h(unsigned v) {
    __half2 h = *reinterpret_cast<__half2*>(&v);
    return __half22float2(h);
}

// ---------------- CSR build ---------------------------------------------------
__global__ void k_count(const int* __restrict__ ei) {
    int e = blockIdx.x * blockDim.x + threadIdx.x;
    if (e < NE) atomicAdd(&g_cnt[clampN(ei[e])], 1);
}

__device__ __forceinline__ int block_incl_scan(int v, int* s_warp) {
    const int lane = threadIdx.x & 31, wid = threadIdx.x >> 5;
    int x = v;
    #pragma unroll
    for (int d = 1; d < 32; d <<= 1) {
        int t = __shfl_up_sync(FULLM, x, d);
        if (lane >= d) x += t;
    }
    if (lane == 31) s_warp[wid] = x;
    __syncthreads();
    if (wid == 0) {
        int y = s_warp[lane];
        #pragma unroll
        for (int d = 1; d < 32; d <<= 1) {
            int t = __shfl_up_sync(FULLM, y, d);
            if (lane >= d) y += t;
        }
        s_warp[lane] = y;
    }
    __syncthreads();
    return x + (wid > 0 ? s_warp[wid - 1] : 0);
}

__global__ void __launch_bounds__(SCAN_B) k_scan1() {
    __shared__ int s_warp[32];
    int i = blockIdx.x * SCAN_B + threadIdx.x;
    int v = (i < NN) ? g_cnt[i] : 0;
    int incl = block_incl_scan(v, s_warp);
    if (i < NN) g_tmp[i] = incl;
    if (threadIdx.x == SCAN_B - 1) g_bsum[blockIdx.x] = incl;
}

__global__ void __launch_bounds__(128) k_scan2() {
    __shared__ int s_warp[32];
    const int lane = threadIdx.x & 31, wid = threadIdx.x >> 5;
    int v = (threadIdx.x < NB_SCAN) ? g_bsum[threadIdx.x] : 0;
    int x = v;
    #pragma unroll
    for (int d = 1; d < 32; d <<= 1) {
        int t = __shfl_up_sync(FULLM, x, d);
        if (lane >= d) x += t;
    }
    if (lane == 31) s_warp[wid] = x;
    __syncthreads();
    if (wid == 0 && lane < 4) {
        int y = s_warp[lane];
        #pragma unroll
        for (int d = 1; d < 4; d <<= 1) {
            int t = __shfl_up_sync(0xfu, y, d);
            if (lane >= d) y += t;
        }
        s_warp[lane] = y;
    }
    __syncthreads();
    int incl = x + (wid > 0 ? s_warp[wid - 1] : 0);
    if (threadIdx.x < NB_SCAN) g_boff[threadIdx.x] = incl - v;
}

// finalize rowptr/cursor/dis/d2/inv, and re-zero g_cnt for next replay
__global__ void __launch_bounds__(SCAN_B) k_scan3() {
    int i = blockIdx.x * SCAN_B + threadIdx.x;
    if (i == 0) g_rowptr[0] = 0;
    if (i < NN) {
        int off  = g_boff[blockIdx.x];
        int incl = g_tmp[i] + off;
        int cnt  = g_cnt[i];
        float dg = fmaxf((float)cnt, 1.0f);
        float ds = rsqrtf(dg);
        g_rowptr[i + 1] = incl;
        g_cursor[i]     = incl - cnt;
        g_dis[i]        = ds;
        g_d2[i]         = 1.0f / dg;      // dis^2 exactly
        g_inv[i]        = sqrtf(dg);      // 1/dis
        g_cnt[i]        = 0;              // ready for next launch
    }
}

// ---------------- merged: scatter (edge blocks) + y GEMM (node blocks) -------
__global__ void __launch_bounds__(256) k_scatter_gemm(const int* __restrict__ ei,
                                                      const float* __restrict__ x,
                                                      const float* __restrict__ W) {
    __shared__ float Wt[HID * WT_PITCH];  // used only by gemm blocks
    const int tid = threadIdx.x;

    if (blockIdx.x < GE_BLOCKS) {
        int e = blockIdx.x * 256 + tid;
        if (e < NE) {
            int r = clampN(ei[e]);
            int c = clampN(ei[NE + e]);
            int pos = atomicAdd(&g_cursor[r], 1);
            g_ecol[pos] = c;
        }
        return;
    }

    // ---- gemm role ----
    for (int idx = tid; idx < NOUT * HID; idx += 256) {
        int o = idx >> 7, k = idx & 127;   // W row-major [o][k]
        Wt[k * WT_PITCH + o] = W[idx];
    }
    __syncthreads();

    const int v = (blockIdx.x - GE_BLOCKS) * 256 + tid;
    if (v >= NN) return;

    const float4* a4 = (const float4*)x + (size_t)v * 32;

    unsigned long long s2[32];
    #pragma unroll
    for (int i = 0; i < 32; ++i) s2[i] = 0ull;

    #pragma unroll 4
    for (int kk = 0; kk < 32; ++kk) {
        float4 a = __ldg(&a4[kk]);
        #pragma unroll
        for (int d = 0; d < 4; ++d) {
            float av = (d == 0) ? a.x : (d == 1) ? a.y : (d == 2) ? a.z : a.w;
            unsigned long long ap;
            asm("mov.b64 %0, {%1, %2};" : "=l"(ap) : "f"(av), "f"(av));
            const unsigned long long* w2 =
                reinterpret_cast<const unsigned long long*>(&Wt[(kk * 4 + d) * WT_PITCH]);
            #pragma unroll
            for (int q = 0; q < 32; ++q) {
                asm("fma.rn.f32x2 %0, %1, %2, %0;" : "+l"(s2[q]) : "l"(ap), "l"(w2[q]));
            }
        }
    }

    const float ds = g_dis[v];
    float2*  yf = (float2*)g_yf + (size_t)v * 32;
    unsigned yh[32];
    #pragma unroll
    for (int q = 0; q < 32; ++q) {
        float l, h;
        asm("mov.b64 {%0, %1}, %2;" : "=f"(l), "=f"(h) : "l"(s2[q]));
        yf[q] = make_float2(l, h);
        yh[q] = pack2h(l * ds, h * ds);
    }
    uint4* yh4 = (uint4*)(g_yh + (size_t)v * 32);
    #pragma unroll
    for (int q = 0; q < 8; ++q)
        yh4[q] = make_uint4(yh[4 * q], yh[4 * q + 1], yh[4 * q + 2], yh[4 * q + 3]);
}

// ---------------- pair-gather: 2 edges/iter, LDG.64, 16 lanes per row --------
// lane = half*16 + sub. Lane accumulates cols [4*sub .. 4*sub+3] over its
// half's edge subset; caller combines halves with shfl_xor(16).
__device__ __forceinline__ float4 gather64p(const unsigned* __restrict__ src,
                                            int beg, int end, int lane,
                                            int half, int sub) {
    float4 a = make_float4(0.f, 0.f, 0.f, 0.f);
    for (int e0 = beg; e0 < end; e0 += 32) {
        int e = e0 + lane;
        int cc = (e < end) ? g_ecol[e] : 0;
        int m = end - e0; if (m > 32) m = 32;
        int j = 0;
        for (; j + 8 <= m; j += 8) {
            int c0 = __shfl_sync(FULLM, cc, j + 0 + half);
            int c1 = __shfl_sync(FULLM, cc, j + 2 + half);
            int c2 = __shfl_sync(FULLM, cc, j + 4 + half);
            int c3 = __shfl_sync(FULLM, cc, j + 6 + half);
            uint2 v0 = __ldg(((const uint2*)(src + (size_t)c0 * 32)) + sub);
            uint2 v1 = __ldg(((const uint2*)(src + (size_t)c1 * 32)) + sub);
            uint2 v2 = __ldg(((const uint2*)(src + (size_t)c2 * 32)) + sub);
            uint2 v3 = __ldg(((const uint2*)(src + (size_t)c3 * 32)) + sub);
            float2 f;
            f = unpack2h(v0.x); a.x += f.x; a.y += f.y;
            f = unpack2h(v0.y); a.z += f.x; a.w += f.y;
            f = unpack2h(v1.x); a.x += f.x; a.y += f.y;
            f = unpack2h(v1.y); a.z += f.x; a.w += f.y;
            f = unpack2h(v2.x); a.x += f.x; a.y += f.y;
            f = unpack2h(v2.y); a.z += f.x; a.w += f.y;
            f = unpack2h(v3.x); a.x += f.x; a.y += f.y;
            f = unpack2h(v3.y); a.z += f.x; a.w += f.y;
        }
        for (; j < m; j += 2) {
            int idx = j + half;
            bool act = idx < m;
            int c = __shfl_sync(FULLM, cc, act ? idx : j);
            uint2 v = __ldg(((const uint2*)(src + (size_t)c * 32)) + sub);
            if (act) {
                float2 f;
                f = unpack2h(v.x); a.x += f.x; a.y += f.y;
                f = unpack2h(v.y); a.z += f.x; a.w += f.y;
            }
        }
    }
    return a;
}

// ---------------- propagate stages (64-dim). STAGE 2 writes final out --------
template <int STAGE>
__global__ void k_prop64(const float* __restrict__ bias, float* __restrict__ out) {
    const int gw   = (blockIdx.x * blockDim.x + threadIdx.x) >> 5;
    const int lane = threadIdx.x & 31;
    const int half = lane >> 4, sub = lane & 15;
    if (gw >= NN) return;
    const unsigned* __restrict__ src =
        (STAGE == 0) ? g_yh : (STAGE == 1) ? g_hA : g_hB;
    float4 a = gather64p(src, g_rowptr[gw], g_rowptr[gw + 1], lane, half, sub);
    // combine the two edge-halves
    a.x += __shfl_xor_sync(FULLM, a.x, 16);
    a.y += __shfl_xor_sync(FULLM, a.y, 16);
    a.z += __shfl_xor_sync(FULLM, a.z, 16);
    a.w += __shfl_xor_sync(FULLM, a.w, 16);

    if (half != 0) return;  // lanes 0-15 own cols 4*sub..4*sub+3

    if (STAGE == 2) {
        float ds  = g_dis[gw];
        float inv = g_inv[gw];
        float4 yv = ((const float4*)g_yf)[(size_t)gw * 16 + sub];
        uint2 h1u = __ldg(((const uint2*)g_hA) + (size_t)gw * 16 + sub);
        uint2 h2u = __ldg(((const uint2*)g_hB) + (size_t)gw * 16 + sub);
        float2 h1a = unpack2h(h1u.x), h1b = unpack2h(h1u.y);
        float2 h2a = unpack2h(h2u.x), h2b = unpack2h(h2u.y);
        float4 bv = __ldg(((const float4*)bias) + sub);
        float4 r;
        r.x = fmaf(0.25f, yv.x + h1a.x * inv + h2a.x * inv + ds * a.x, bv.x);
        r.y = fmaf(0.25f, yv.y + h1a.y * inv + h2a.y * inv + ds * a.y, bv.y);
        r.z = fmaf(0.25f, yv.z + h1b.x * inv + h2b.x * inv + ds * a.z, bv.z);
        r.w = fmaf(0.25f, yv.w + h1b.y * inv + h2b.y * inv + ds * a.w, bv.w);
        ((float4*)out)[(size_t)gw * 16 + sub] = r;
    } else {
        float d2 = g_d2[gw];
        uint2 p;
        p.x = pack2h(d2 * a.x, d2 * a.y);
        p.y = pack2h(d2 * a.z, d2 * a.w);
        uint2* dst = (STAGE == 1) ? (uint2*)g_hB : (uint2*)g_hA;
        dst[(size_t)gw * 16 + sub] = p;
    }
}

// ---------------- launch -----------------------------------------------------
extern "C" void kernel_launch(void* const* d_in, const int* in_sizes, int n_in,
                              void* d_out, int out_size) {
    const float* x   = (const float*)d_in[0];   // [NN, HID]
    const int*   ei  = (const int*)d_in[1];     // [2, NE] int32
    const float* W   = (const float*)d_in[2];   // [NOUT, HID]
    const float* b   = (const float*)d_in[3];   // [NOUT]
    float*       out = (float*)d_out;           // [NN, NOUT]

    const int TB = 256;
    const int gE = (NE + TB - 1) / TB;
    const int gP = (NN * 32 + TB - 1) / TB;   // warp per node

    // g_cnt is zero on entry (zero-init on load; k_scan3 re-zeroes each launch)
    k_count<<<gE, TB>>>(ei);                        // launch 0
    k_scan1<<<NB_SCAN, SCAN_B>>>();                 // launch 1
    k_scan2<<<1, 128>>>();                          // launch 2
    k_scan3<<<NB_SCAN, SCAN_B>>>();                 // launch 3
    k_scatter_gemm<<<GE_BLOCKS + GG_BLOCKS, TB>>>(ei, x, W);  // launch 4

    k_prop64<0><<<gP, TB>>>(b, out);                // launch 5  (profiled)
    k_prop64<1><<<gP, TB>>>(b, out);                // launch 6
    k_prop64<2><<<gP, TB>>>(b, out);                // launch 7

    (void)in_sizes; (void)n_in; (void)out_size;
}

// round 14
// speedup vs baseline: 1.3699x; 1.3699x over previous
#include <cuda_runtime.h>
#include <cuda_fp16.h>

#define NN   100000
#define NE   1600000
#define HID  128
#define NOUT 64
#define FULLM 0xffffffffu
#define SCAN_B 1024
#define NB_SCAN ((NN + SCAN_B - 1) / SCAN_B)   // 98
#define WT_PITCH 66

// ---------------- scratch (device globals; zero-initialized at load) ---------
__device__ int      g_cnt[NN];            // starts 0; re-zeroed by k_scan3
__device__ int      g_tmp[NN];
__device__ int      g_bsum[NB_SCAN];
__device__ int      g_boff[NB_SCAN];
__device__ int      g_rowptr[NN + 1];
__device__ int      g_cursor[NN];
__device__ float    g_dis[NN];            // deg^-1/2 (clamped)
__device__ float    g_d2[NN];             // dis^2
__device__ float    g_inv[NN];            // 1/dis
__device__ int      g_ecol[NE];           // edge cols (CSR order)
__device__ float    g_yf[(size_t)NN * NOUT];     // y = x @ W^T, fp32
__device__ unsigned g_yh[(size_t)NN * 32];       // dis*y in half (64 half)
__device__ unsigned g_hA[(size_t)NN * 32];       // dis^2 * S0
__device__ unsigned g_hB[(size_t)NN * 32];       // dis^2 * S1

__device__ __forceinline__ int clampN(int v) {
    v = v < 0 ? 0 : v;
    return v >= NN ? NN - 1 : v;
}

__device__ __forceinline__ unsigned pack2h(float a, float b) {
    __half2 h = __floats2half2_rn(a, b);
    return *reinterpret_cast<unsigned*>(&h);
}

__device__ __forceinline__ float2 unpack2h(unsigned v) {
    __half2 h = *reinterpret_cast<__half2*>(&v);
    return __half22float2(h);
}

// ---------------- CSR build: 2 edges/thread (int2 loads) ----------------------
__global__ void k_count(const int2* __restrict__ ei2) {
    int t = blockIdx.x * blockDim.x + threadIdx.x;
    if (t < NE / 2) {
        int2 rr = ei2[t];
        atomicAdd(&g_cnt[clampN(rr.x)], 1);
        atomicAdd(&g_cnt[clampN(rr.y)], 1);
    }
}

__device__ __forceinline__ int block_incl_scan(int v, int* s_warp) {
    const int lane = threadIdx.x & 31, wid = threadIdx.x >> 5;
    int x = v;
    #pragma unroll
    for (int d = 1; d < 32; d <<= 1) {
        int t = __shfl_up_sync(FULLM, x, d);
        if (lane >= d) x += t;
    }
    if (lane == 31) s_warp[wid] = x;
    __syncthreads();
    if (wid == 0) {
        int y = s_warp[lane];
        #pragma unroll
        for (int d = 1; d < 32; d <<= 1) {
            int t = __shfl_up_sync(FULLM, y, d);
            if (lane >= d) y += t;
        }
        s_warp[lane] = y;
    }
    __syncthreads();
    return x + (wid > 0 ? s_warp[wid - 1] : 0);
}

__global__ void __launch_bounds__(SCAN_B) k_scan1() {
    __shared__ int s_warp[32];
    int i = blockIdx.x * SCAN_B + threadIdx.x;
    int v = (i < NN) ? g_cnt[i] : 0;
    int incl = block_incl_scan(v, s_warp);
    if (i < NN) g_tmp[i] = incl;
    if (threadIdx.x == SCAN_B - 1) g_bsum[blockIdx.x] = incl;
}

__global__ void __launch_bounds__(128) k_scan2() {
    __shared__ int s_warp[32];
    const int lane = threadIdx.x & 31, wid = threadIdx.x >> 5;
    int v = (threadIdx.x < NB_SCAN) ? g_bsum[threadIdx.x] : 0;
    int x = v;
    #pragma unroll
    for (int d = 1; d < 32; d <<= 1) {
        int t = __shfl_up_sync(FULLM, x, d);
        if (lane >= d) x += t;
    }
    if (lane == 31) s_warp[wid] = x;
    __syncthreads();
    if (wid == 0 && lane < 4) {
        int y = s_warp[lane];
        #pragma unroll
        for (int d = 1; d < 4; d <<= 1) {
            int t = __shfl_up_sync(0xfu, y, d);
            if (lane >= d) y += t;
        }
        s_warp[lane] = y;
    }
    __syncthreads();
    int incl = x + (wid > 0 ? s_warp[wid - 1] : 0);
    if (threadIdx.x < NB_SCAN) g_boff[threadIdx.x] = incl - v;
}

// finalize rowptr/cursor/dis/d2/inv, and re-zero g_cnt for next replay
__global__ void __launch_bounds__(SCAN_B) k_scan3() {
    int i = blockIdx.x * SCAN_B + threadIdx.x;
    if (i == 0) g_rowptr[0] = 0;
    if (i < NN) {
        int off  = g_boff[blockIdx.x];
        int incl = g_tmp[i] + off;
        int cnt  = g_cnt[i];
        float dg = fmaxf((float)cnt, 1.0f);
        float ds = rsqrtf(dg);
        g_rowptr[i + 1] = incl;
        g_cursor[i]     = incl - cnt;
        g_dis[i]        = ds;
        g_d2[i]         = 1.0f / dg;      // dis^2 exactly
        g_inv[i]        = sqrtf(dg);      // 1/dis
        g_cnt[i]        = 0;              // ready for next launch
    }
}

// 2 edges/thread scatter
__global__ void k_scatter(const int* __restrict__ ei) {
    int t = blockIdx.x * blockDim.x + threadIdx.x;
    if (t < NE / 2) {
        int2 rr = ((const int2*)ei)[t];
        int2 cc = ((const int2*)(ei + NE))[t];
        int r0 = clampN(rr.x), c0 = clampN(cc.x);
        int r1 = clampN(rr.y), c1 = clampN(cc.y);
        int p0 = atomicAdd(&g_cursor[r0], 1);
        g_ecol[p0] = c0;
        int p1 = atomicAdd(&g_cursor[r1], 1);
        g_ecol[p1] = c1;
    }
}

// ---------------- y = x @ W^T (fp32 out) + scaled half ŷ = dis*y -------------
__global__ void __launch_bounds__(128) k_gemm_y(const float* __restrict__ x,
                                                const float* __restrict__ W) {
    __shared__ float Wt[HID * WT_PITCH];  // Wt[k*66 + o]
    const int tid = threadIdx.x;
    for (int idx = tid; idx < NOUT * HID; idx += 128) {
        int o = idx >> 7, k = idx & 127;   // W row-major [o][k]
        Wt[k * WT_PITCH + o] = W[idx];
    }
    __syncthreads();

    const int v = blockIdx.x * 128 + tid;
    if (v >= NN) return;

    const float4* a4 = (const float4*)x + (size_t)v * 32;

    unsigned long long s2[32];
    #pragma unroll
    for (int i = 0; i < 32; ++i) s2[i] = 0ull;

    #pragma unroll 4
    for (int kk = 0; kk < 32; ++kk) {
        float4 a = __ldg(&a4[kk]);
        #pragma unroll
        for (int d = 0; d < 4; ++d) {
            float av = (d == 0) ? a.x : (d == 1) ? a.y : (d == 2) ? a.z : a.w;
            unsigned long long ap;
            asm("mov.b64 %0, {%1, %2};" : "=l"(ap) : "f"(av), "f"(av));
            const unsigned long long* w2 =
                reinterpret_cast<const unsigned long long*>(&Wt[(kk * 4 + d) * WT_PITCH]);
            #pragma unroll
            for (int q = 0; q < 32; ++q) {
                asm("fma.rn.f32x2 %0, %1, %2, %0;" : "+l"(s2[q]) : "l"(ap), "l"(w2[q]));
            }
        }
    }

    const float ds = g_dis[v];
    float2*  yf = (float2*)g_yf + (size_t)v * 32;
    unsigned yh[32];
    #pragma unroll
    for (int q = 0; q < 32; ++q) {
        float l, h;
        asm("mov.b64 {%0, %1}, %2;" : "=f"(l), "=f"(h) : "l"(s2[q]));
        yf[q] = make_float2(l, h);
        yh[q] = pack2h(l * ds, h * ds);
    }
    uint4* yh4 = (uint4*)(g_yh + (size_t)v * 32);
    #pragma unroll
    for (int q = 0; q < 8; ++q)
        yh4[q] = make_uint4(yh[4 * q], yh[4 * q + 1], yh[4 * q + 2], yh[4 * q + 3]);
}

// ---------------- gather: warp per node, unweighted sum of prescaled rows ----
__device__ __forceinline__ float2 gather64(const unsigned* __restrict__ src,
                                           int beg, int end, int lane) {
    float ax = 0.f, ay = 0.f;
    for (int e0 = beg; e0 < end; e0 += 32) {
        int e = e0 + lane;
        int cc = (e < end) ? g_ecol[e] : 0;
        int m = end - e0; if (m > 32) m = 32;
        int j = 0;
        for (; j + 8 <= m; j += 8) {
            int c0 = __shfl_sync(FULLM, cc, j + 0);
            int c1 = __shfl_sync(FULLM, cc, j + 1);
            int c2 = __shfl_sync(FULLM, cc, j + 2);
            int c3 = __shfl_sync(FULLM, cc, j + 3);
            int c4 = __shfl_sync(FULLM, cc, j + 4);
            int c5 = __shfl_sync(FULLM, cc, j + 5);
            int c6 = __shfl_sync(FULLM, cc, j + 6);
            int c7 = __shfl_sync(FULLM, cc, j + 7);
            unsigned v0 = __ldg(&src[(size_t)c0 * 32 + lane]);
            unsigned v1 = __ldg(&src[(size_t)c1 * 32 + lane]);
            unsigned v2 = __ldg(&src[(size_t)c2 * 32 + lane]);
            unsigned v3 = __ldg(&src[(size_t)c3 * 32 + lane]);
            unsigned v4 = __ldg(&src[(size_t)c4 * 32 + lane]);
            unsigned v5 = __ldg(&src[(size_t)c5 * 32 + lane]);
            unsigned v6 = __ldg(&src[(size_t)c6 * 32 + lane]);
            unsigned v7 = __ldg(&src[(size_t)c7 * 32 + lane]);
            float2 f;
            f = unpack2h(v0); ax += f.x; ay += f.y;
            f = unpack2h(v1); ax += f.x; ay += f.y;
            f = unpack2h(v2); ax += f.x; ay += f.y;
            f = unpack2h(v3); ax += f.x; ay += f.y;
            f = unpack2h(v4); ax += f.x; ay += f.y;
            f = unpack2h(v5); ax += f.x; ay += f.y;
            f = unpack2h(v6); ax += f.x; ay += f.y;
            f = unpack2h(v7); ax += f.x; ay += f.y;
        }
        for (; j < m; ++j) {
            int c0 = __shfl_sync(FULLM, cc, j);
            float2 f = unpack2h(__ldg(&src[(size_t)c0 * 32 + lane]));
            ax += f.x; ay += f.y;
        }
    }
    return make_float2(ax, ay);
}

// ---------------- propagate stages (64-dim). STAGE 2 writes final out --------
// STAGE 0: S = sum(yh[col]);  hA = dis^2 * S    (= dis * h1)
// STAGE 1: S = sum(hA[col]);  hB = dis^2 * S    (= dis * h2)
// STAGE 2: S = sum(hB[col]);  out = 0.25*(y + hA*inv + hB*inv + dis*S) + b
template <int STAGE>
__global__ void k_prop64(const float* __restrict__ bias, float* __restrict__ out) {
    const int gw   = (blockIdx.x * blockDim.x + threadIdx.x) >> 5;
    const int lane = threadIdx.x & 31;
    if (gw >= NN) return;
    const unsigned* __restrict__ src =
        (STAGE == 0) ? g_yh : (STAGE == 1) ? g_hA : g_hB;
    float2 a = gather64(src, g_rowptr[gw], g_rowptr[gw + 1], lane);
    const size_t o = (size_t)gw * 32 + lane;
    if (STAGE == 2) {
        float ds  = g_dis[gw];
        float inv = g_inv[gw];
        float2 yv = ((const float2*)g_yf)[o];
        float2 h1 = unpack2h(__ldg(&g_hA[o]));
        float2 h2 = unpack2h(__ldg(&g_hB[o]));
        float2 bv = __ldg((const float2*)bias + lane);
        float2 r;
        r.x = fmaf(0.25f, yv.x + h1.x * inv + h2.x * inv + ds * a.x, bv.x);
        r.y = fmaf(0.25f, yv.y + h1.y * inv + h2.y * inv + ds * a.y, bv.y);
        ((float2*)out)[o] = r;
    } else {
        float d2 = g_d2[gw];
        unsigned p = pack2h(d2 * a.x, d2 * a.y);
        if (STAGE == 1) g_hB[o] = p;
        else            g_hA[o] = p;
    }
}

// ---------------- launch -----------------------------------------------------
extern "C" void kernel_launch(void* const* d_in, const int* in_sizes, int n_in,
                              void* d_out, int out_size) {
    const float* x   = (const float*)d_in[0];   // [NN, HID]
    const int*   ei  = (const int*)d_in[1];     // [2, NE] int32
    const float* W   = (const float*)d_in[2];   // [NOUT, HID]
    const float* b   = (const float*)d_in[3];   // [NOUT]
    float*       out = (float*)d_out;           // [NN, NOUT]

    const int TB = 256;
    const int gE2 = (NE / 2 + TB - 1) / TB;   // 2 edges per thread
    const int gP  = (NN * 32 + TB - 1) / TB;  // warp per node
    const int gG  = (NN + 127) / 128;

    // g_cnt is zero on entry (zero-init on load; k_scan3 re-zeroes each launch)
    k_count<<<gE2, TB>>>((const int2*)ei);
    k_scan1<<<NB_SCAN, SCAN_B>>>();
    k_scan2<<<1, 128>>>();
    k_scan3<<<NB_SCAN, SCAN_B>>>();           // rowptr/cursor/dis/d2/inv + cnt=0
    k_scatter<<<gE2, TB>>>(ei);
    k_gemm_y<<<gG, 128>>>(x, W);              // y fp32 + ŷ=dis*y half

    k_prop64<0><<<gP, TB>>>(b, out);          // ŷ  -> hA
    k_prop64<1><<<gP, TB>>>(b, out);          // hA -> hB
    k_prop64<2><<<gP, TB>>>(b, out);          // hB -> out (mean+bias fused)

    (void)in_sizes; (void)n_in; (void)out_size;
}